// round 1
// baseline (speedup 1.0000x reference)
#include <cuda_runtime.h>
#include <stdint.h>

#define B_SZ 1024
#define D_SZ 128
#define V_SZ 100000
#define VP_SZ 100096           // padded to 782*128
#define S_SZ 100
#define K_TOP 500
#define NEG_INF_F (-1e30f)

#define BM 128
#define BN 128
#define BK 32
#define TM 8
#define TN 8

#define NB_MAX 4096
#define CAND_MAX 2048

// Scratch: scores [B][VP]  (~410 MB, static device allocation: allowed)
__device__ float d_scores[(size_t)B_SZ * VP_SZ];
__device__ int d_seed_is32;

// ---------------------------------------------------------------------------
// Seed-dtype detection: jnp.int64 silently demotes to int32 without x64.
// Read the buffer as u64: true int64 values (< 100000) have zero high words;
// int32 data puts the odd-indexed values in the high words (almost surely
// nonzero somewhere among 51200 of them).
// ---------------------------------------------------------------------------
__global__ void detect_seed_kernel(const unsigned long long* __restrict__ seeds) {
    __shared__ unsigned int sflag;
    if (threadIdx.x == 0) sflag = 0u;
    __syncthreads();
    unsigned int loc = 0u;
    for (int i = threadIdx.x; i < 51200; i += blockDim.x) {
        loc |= (unsigned int)(seeds[i] >> 32);
    }
    if (loc) atomicOr(&sflag, 1u);
    __syncthreads();
    if (threadIdx.x == 0) d_seed_is32 = (sflag != 0u) ? 1 : 0;
}

// ---------------------------------------------------------------------------
// SGEMM: C[b][v] = sum_d A[b][d] * T[v][d]   (both K-major, A @ T^T)
// 128x128 tile, BK=32, 256 threads, 8x8 per thread, fp32 FMA.
// ---------------------------------------------------------------------------
__global__ __launch_bounds__(256) void gemm_kernel(const float* __restrict__ A,
                                                   const float* __restrict__ Tb) {
    __shared__ float As[BK][BM];
    __shared__ float Bs[BK][BN];
    const int bx = blockIdx.x;   // V tile
    const int by = blockIdx.y;   // B tile
    const int tid = threadIdx.x;
    const int tcol = tid % 16;
    const int trow = tid / 16;
    const int innerRow = tid / 8;        // 0..31
    const int innerCol = (tid % 8) * 4;  // k offset: 0,4,...,28

    float acc[TM][TN];
    #pragma unroll
    for (int m = 0; m < TM; m++)
        #pragma unroll
        for (int n = 0; n < TN; n++) acc[m][n] = 0.0f;

    const int aRowBase = by * BM;
    const int bRowBase = bx * BN;

    for (int kt = 0; kt < D_SZ; kt += BK) {
        #pragma unroll
        for (int i = 0; i < 4; i++) {
            int r = innerRow + i * 32;
            float4 v = *(const float4*)&A[(size_t)(aRowBase + r) * D_SZ + kt + innerCol];
            As[innerCol + 0][r] = v.x;
            As[innerCol + 1][r] = v.y;
            As[innerCol + 2][r] = v.z;
            As[innerCol + 3][r] = v.w;
        }
        #pragma unroll
        for (int i = 0; i < 4; i++) {
            int r = innerRow + i * 32;
            int vrow = bRowBase + r;
            float4 t = make_float4(0.f, 0.f, 0.f, 0.f);
            if (vrow < V_SZ)
                t = *(const float4*)&Tb[(size_t)vrow * D_SZ + kt + innerCol];
            Bs[innerCol + 0][r] = t.x;
            Bs[innerCol + 1][r] = t.y;
            Bs[innerCol + 2][r] = t.z;
            Bs[innerCol + 3][r] = t.w;
        }
        __syncthreads();

        #pragma unroll
        for (int kk = 0; kk < BK; kk++) {
            float ra[TM], rb[TN];
            #pragma unroll
            for (int m = 0; m < TM; m++) ra[m] = As[kk][trow * TM + m];
            #pragma unroll
            for (int n = 0; n < TN; n++) rb[n] = Bs[kk][tcol * TN + n];
            #pragma unroll
            for (int m = 0; m < TM; m++)
                #pragma unroll
                for (int n = 0; n < TN; n++)
                    acc[m][n] = fmaf(ra[m], rb[n], acc[m][n]);
        }
        __syncthreads();
    }

    #pragma unroll
    for (int m = 0; m < TM; m++) {
        size_t base = (size_t)(aRowBase + trow * TM + m) * VP_SZ + bRowBase + tcol * TN;
        *(float4*)&d_scores[base + 0] = make_float4(acc[m][0], acc[m][1], acc[m][2], acc[m][3]);
        *(float4*)&d_scores[base + 4] = make_float4(acc[m][4], acc[m][5], acc[m][6], acc[m][7]);
    }
}

// ---------------------------------------------------------------------------
// Mask seed tracks to NEG_INF.
// ---------------------------------------------------------------------------
__global__ void mask_kernel(const void* __restrict__ seeds) {
    int i = blockIdx.x * blockDim.x + threadIdx.x;
    if (i >= B_SZ * S_SZ) return;
    long long idx;
    if (d_seed_is32) idx = (long long)((const int*)seeds)[i];
    else             idx = ((const long long*)seeds)[i];
    int b = i / S_SZ;
    d_scores[(size_t)b * VP_SZ + (size_t)idx] = NEG_INF_F;
}

// ---------------------------------------------------------------------------
// Top-K selection per row: radix select (order-preserving uint keys,
// histogram on top bits, refine only if boundary bin too fat), collect
// candidates, bitonic-sort (key desc, idx asc) in shared, emit top 500.
// ---------------------------------------------------------------------------
__device__ __forceinline__ unsigned int fkey(float f) {
    unsigned int u = __float_as_uint(f);
    return (u & 0x80000000u) ? ~u : (u | 0x80000000u);
}
__device__ __forceinline__ float keyToFloat(unsigned int u) {
    unsigned int b = (u & 0x80000000u) ? (u & 0x7FFFFFFFu) : ~u;
    return __uint_as_float(b);
}

__global__ __launch_bounds__(256) void topk_kernel(float* __restrict__ out, int half) {
    const int b = blockIdx.x;
    const int tid = threadIdx.x;
    const float* __restrict__ row = d_scores + (size_t)b * VP_SZ;

    __shared__ int hist[NB_MAX];
    __shared__ int chunkSum[256];
    __shared__ unsigned int candKey[CAND_MAX];
    __shared__ int candIdx[CAND_MAX];
    __shared__ unsigned int s_thresh;
    __shared__ int s_r, s_cand, s_count;

    unsigned int mask = 0u, val = 0u;
    int r = K_TOP;
    const int shifts[3] = {20, 8, 0};
    const int bitsv[3] = {12, 12, 8};

    unsigned int thresh = 0u;
    for (int lvl = 0; lvl < 3; lvl++) {
        const int nb = 1 << bitsv[lvl];
        const int sh = shifts[lvl];

        for (int i = tid; i < nb; i += 256) hist[i] = 0;
        __syncthreads();

        for (int i = tid; i < V_SZ / 4; i += 256) {
            float4 f = ((const float4*)row)[i];
            unsigned int u;
            u = fkey(f.x); if ((u & mask) == val) atomicAdd(&hist[(u >> sh) & (nb - 1)], 1);
            u = fkey(f.y); if ((u & mask) == val) atomicAdd(&hist[(u >> sh) & (nb - 1)], 1);
            u = fkey(f.z); if ((u & mask) == val) atomicAdd(&hist[(u >> sh) & (nb - 1)], 1);
            u = fkey(f.w); if ((u & mask) == val) atomicAdd(&hist[(u >> sh) & (nb - 1)], 1);
        }
        __syncthreads();

        const int cs = (nb + 255) / 256;
        {
            int lo = tid * cs;
            int hi = min(nb, lo + cs);
            int s = 0;
            for (int i = lo; i < hi; i++) s += hist[i];
            chunkSum[tid] = s;
        }
        __syncthreads();

        if (tid == 0) {
            int acc = 0, bsel = -1;
            for (int c = 255; c >= 0; c--) {
                int clo = c * cs;
                if (clo >= nb) continue;
                int chi = min(nb, clo + cs);
                if (acc + chunkSum[c] >= r) {
                    for (int bn = chi - 1; bn >= clo; bn--) {
                        if (acc + hist[bn] >= r) { bsel = bn; break; }
                        acc += hist[bn];
                    }
                    break;
                }
                acc += chunkSum[c];
            }
            int rn = r - acc;  // rank within boundary bin
            s_thresh = val | ((unsigned int)bsel << sh);
            s_r = rn;
            s_cand = (K_TOP - rn) + hist[bsel];
        }
        __syncthreads();
        thresh = s_thresh;
        int rn = s_r;
        int cand = s_cand;
        if (cand <= CAND_MAX || lvl == 2) break;
        mask |= (unsigned int)(nb - 1) << sh;
        val = thresh;
        r = rn;
    }

    // Collect candidates: all elements with key >= thresh.
    if (tid == 0) s_count = 0;
    __syncthreads();
    for (int i = tid; i < V_SZ / 4; i += 256) {
        float4 f = ((const float4*)row)[i];
        unsigned int u;
        u = fkey(f.x); if (u >= thresh) { int p = atomicAdd(&s_count, 1); if (p < CAND_MAX) { candKey[p] = u; candIdx[p] = 4 * i + 0; } }
        u = fkey(f.y); if (u >= thresh) { int p = atomicAdd(&s_count, 1); if (p < CAND_MAX) { candKey[p] = u; candIdx[p] = 4 * i + 1; } }
        u = fkey(f.z); if (u >= thresh) { int p = atomicAdd(&s_count, 1); if (p < CAND_MAX) { candKey[p] = u; candIdx[p] = 4 * i + 2; } }
        u = fkey(f.w); if (u >= thresh) { int p = atomicAdd(&s_count, 1); if (p < CAND_MAX) { candKey[p] = u; candIdx[p] = 4 * i + 3; } }
    }
    __syncthreads();
    int n = min(s_count, CAND_MAX);
    for (int i = n + tid; i < CAND_MAX; i += 256) {
        candKey[i] = 0u;
        candIdx[i] = 0x7FFFFFFF;
    }
    __syncthreads();

    // Bitonic sort, 2048 elements: descending by key, ascending idx on ties
    // (matches jax.lax.top_k tie-break: lower index first).
    for (int k = 2; k <= CAND_MAX; k <<= 1) {
        for (int j = k >> 1; j > 0; j >>= 1) {
            for (int i = tid; i < CAND_MAX; i += 256) {
                int ixj = i ^ j;
                if (ixj > i) {
                    unsigned int ki = candKey[i], kj = candKey[ixj];
                    int ii = candIdx[i], ij = candIdx[ixj];
                    // "i precedes ixj" in global descending order:
                    bool before_ij = (ki > kj) || (ki == kj && ii < ij);
                    bool descRegion = ((i & k) == 0);
                    bool doswap = descRegion ? (!before_ij) : before_ij;
                    if (doswap) {
                        candKey[i] = kj; candKey[ixj] = ki;
                        candIdx[i] = ij; candIdx[ixj] = ii;
                    }
                }
            }
            __syncthreads();
        }
    }

    for (int i = tid; i < K_TOP; i += 256) {
        out[b * K_TOP + i] = keyToFloat(candKey[i]);
        out[half + b * K_TOP + i] = (float)candIdx[i];
    }
}

// ---------------------------------------------------------------------------
extern "C" void kernel_launch(void* const* d_in, const int* in_sizes, int n_in,
                              void* d_out, int out_size) {
    const float* gen   = (const float*)d_in[0];   // [1024,128] f32
    const void*  seeds = d_in[1];                 // [1024,100] int32 or int64
    const float* table = (const float*)d_in[2];   // [100000,128] f32
    float* out = (float*)d_out;

    detect_seed_kernel<<<1, 256>>>((const unsigned long long*)seeds);

    dim3 g(VP_SZ / BN, B_SZ / BM);
    gemm_kernel<<<g, 256>>>(gen, table);

    mask_kernel<<<(B_SZ * S_SZ + 255) / 256, 256>>>(seeds);

    topk_kernel<<<B_SZ, 256>>>(out, out_size / 2);
}

// round 4
// speedup vs baseline: 1.2344x; 1.2344x over previous
#include <cuda_runtime.h>
#include <cuda_fp16.h>
#include <stdint.h>

#define B_SZ 1024
#define D_SZ 128
#define V_SZ 100000
#define VP_SZ 100096           // padded to 782*128 (mult of 8 for uint4 loads)
#define S_SZ 100
#define K_TOP 500
#define R_SEL 640              // approx-rank cutoff for candidate collection
#define HALF_NEG_INF 0xFC00u

#define NB_MAX 4096
#define CAND_MAX 2048
#define NT_TILES 782

// ---------------------------------------------------------------------------
// Device globals (static allocations are allowed)
// ---------------------------------------------------------------------------
__device__ unsigned short d_scores_h[(size_t)B_SZ * VP_SZ];   // fp16 approx scores, 205 MB
__device__ int d_seed_is32;

// ---------------------------------------------------------------------------
__device__ __forceinline__ void mma_tf32(float* d, const float4& a, const float2& b) {
    asm volatile(
        "mma.sync.aligned.m16n8k8.row.col.f32.tf32.tf32.f32 "
        "{%0,%1,%2,%3}, {%4,%5,%6,%7}, {%8,%9}, {%0,%1,%2,%3};"
        : "+f"(d[0]), "+f"(d[1]), "+f"(d[2]), "+f"(d[3])
        : "r"(__float_as_uint(a.x)), "r"(__float_as_uint(a.y)),
          "r"(__float_as_uint(a.z)), "r"(__float_as_uint(a.w)),
          "r"(__float_as_uint(b.x)), "r"(__float_as_uint(b.y)));
}

// ---------------------------------------------------------------------------
// Seed-dtype detection (int64 vs silently-demoted int32)
// ---------------------------------------------------------------------------
__global__ void detect_seed_kernel(const unsigned long long* __restrict__ seeds) {
    __shared__ unsigned int sflag;
    if (threadIdx.x == 0) sflag = 0u;
    __syncthreads();
    unsigned int loc = 0u;
    for (int i = threadIdx.x; i < 51200; i += blockDim.x)
        loc |= (unsigned int)(seeds[i] >> 32);
    if (loc) atomicOr(&sflag, 1u);
    __syncthreads();
    if (threadIdx.x == 0) d_seed_is32 = (sflag != 0u) ? 1 : 0;
}

// ---------------------------------------------------------------------------
// Single-term tf32 GEMM via mma.sync.m16n8k8 (raw fp32 bits fed as tf32 —
// truncation error irrelevant, selection margin covers it).
// CTA 128x128, 8 warps (4Mx2N), K in 4 chunks of 32, fragment-major smem
// (layout validated in R3: values matched at 1e-6). Epilogue stages through
// smem as fp16 and stores coalesced 16B lines.
// Smem: sA 16 KB + sB 16 KB, reused as 32 KB fp16 staging for epilogue.
// ---------------------------------------------------------------------------
__global__ __launch_bounds__(256) void gemm_tf32_kernel(const float* __restrict__ gen,
                                                        const float* __restrict__ table) {
    extern __shared__ float sm[];
    float* sA = sm;             // 4096 floats
    float* sB = sm + 4096;      // 4096 floats
    __half* sh = (__half*)sm;   // epilogue staging: 16384 halves

    const int tid = threadIdx.x;
    const int lane = tid & 31;
    const int w = tid >> 5;
    const int warpM = w & 3;
    const int warpN = w >> 2;
    const int nt = blockIdx.x;
    const int by = blockIdx.y;

    const int frow = tid >> 1;
    const int fhalf = tid & 1;

    const float* gA = gen + (size_t)(by * 128 + frow) * D_SZ + fhalf * 16;
    const int brow = min(nt * 128 + frow, V_SZ - 1);   // clamp: last tile reads row V-1
    const float* gB = table + (size_t)brow * D_SZ + fhalf * 16;

    float acc[2][8][4];
    #pragma unroll
    for (int mf = 0; mf < 2; mf++)
        #pragma unroll
        for (int nf = 0; nf < 8; nf++)
            #pragma unroll
            for (int r = 0; r < 4; r++) acc[mf][nf][r] = 0.0f;

    float4 stA[4], stB[4];
    #pragma unroll
    for (int q = 0; q < 4; q++) {
        stA[q] = *(const float4*)(gA + q * 4);
        stB[q] = *(const float4*)(gB + q * 4);
    }

    const int a_reg_half = (frow & 15) >> 3;
    const int a_mblock = frow >> 4;
    const int b_nblock = frow >> 3;
    const int tbase = (frow & 7) * 4;

    for (int c = 0; c < 4; c++) {
        if (c > 0) __syncthreads();

        #pragma unroll
        for (int q = 0; q < 4; q++) {
            const int kl0 = fhalf * 16 + q * 4;
            const int kstep = kl0 >> 3;
            const int regb = (kl0 & 7) >> 2;
            {
                const int base = ((kstep * 8 + a_mblock) * 32 + tbase) * 4 + regb * 2 + a_reg_half;
                float4 v = stA[q];
                sA[base + 0] = v.x; sA[base + 4] = v.y; sA[base + 8] = v.z; sA[base + 12] = v.w;
            }
            {
                const int base = ((kstep * 16 + b_nblock) * 32 + tbase) * 2 + regb;
                float4 v = stB[q];
                sB[base + 0] = v.x; sB[base + 2] = v.y; sB[base + 4] = v.z; sB[base + 6] = v.w;
            }
        }
        __syncthreads();

        if (c < 3) {
            const int off = (c + 1) * 32;
            #pragma unroll
            for (int q = 0; q < 4; q++) {
                stA[q] = *(const float4*)(gA + off + q * 4);
                stB[q] = *(const float4*)(gB + off + q * 4);
            }
        }

        #pragma unroll
        for (int ks = 0; ks < 4; ks++) {
            float4 af[2];
            #pragma unroll
            for (int mf = 0; mf < 2; mf++) {
                const int idx = ((ks * 8 + warpM * 2 + mf) * 32 + lane) * 4;
                af[mf] = *(const float4*)(sA + idx);
            }
            #pragma unroll
            for (int nf = 0; nf < 8; nf++) {
                const int bidx = ((ks * 16 + warpN * 8 + nf) * 32 + lane) * 2;
                const float2 bv = *(const float2*)(sB + bidx);
                #pragma unroll
                for (int mf = 0; mf < 2; mf++)
                    mma_tf32(acc[mf][nf], af[mf], bv);
            }
        }
    }

    // Epilogue: regs -> smem fp16 -> coalesced gmem
    __syncthreads();
    #pragma unroll
    for (int mf = 0; mf < 2; mf++) {
        const int row = warpM * 32 + mf * 16 + (lane >> 2);
        #pragma unroll
        for (int nf = 0; nf < 8; nf++) {
            const int col = warpN * 64 + nf * 8 + (lane & 3) * 2;
            *(__half2*)(sh + row * 128 + col) =
                __floats2half2_rn(acc[mf][nf][0], acc[mf][nf][1]);
            *(__half2*)(sh + (row + 8) * 128 + col) =
                __floats2half2_rn(acc[mf][nf][2], acc[mf][nf][3]);
        }
    }
    __syncthreads();
    #pragma unroll
    for (int i = 0; i < 8; i++) {
        const int t = tid + i * 256;       // 0..2047
        const int r = t >> 4;
        const int c16 = (t & 15) * 8;      // 8 halves = 16 B
        uint4 v = *(uint4*)(sh + r * 128 + c16);
        *(uint4*)&d_scores_h[(size_t)(by * 128 + r) * VP_SZ + nt * 128 + c16] = v;
    }
}

// ---------------------------------------------------------------------------
// Pad: cols [V, VP) -> -inf (overwrites the clamped-row garbage of tile 781)
// ---------------------------------------------------------------------------
__global__ void pad_kernel() {
    int i = blockIdx.x * blockDim.x + threadIdx.x;
    int n = B_SZ * (VP_SZ - V_SZ);
    if (i >= n) return;
    int b = i / (VP_SZ - V_SZ);
    int j = i % (VP_SZ - V_SZ);
    d_scores_h[(size_t)b * VP_SZ + V_SZ + j] = (unsigned short)HALF_NEG_INF;
}

// ---------------------------------------------------------------------------
// Mask seed tracks to -inf (fp16).
// ---------------------------------------------------------------------------
__global__ void mask_kernel(const void* __restrict__ seeds) {
    int i = blockIdx.x * blockDim.x + threadIdx.x;
    if (i >= B_SZ * S_SZ) return;
    long long idx;
    if (d_seed_is32) idx = (long long)((const int*)seeds)[i];
    else             idx = ((const long long*)seeds)[i];
    int b = i / S_SZ;
    d_scores_h[(size_t)b * VP_SZ + (size_t)idx] = (unsigned short)HALF_NEG_INF;
}

// ---------------------------------------------------------------------------
// Per-row: radix-select approx threshold at rank R_SEL, collect candidate
// indices, EXACT fp32 rescore (sequential-k fmaf — bit-matches reference),
// bitonic sort by exact (desc, idx asc), emit top-500.
// ---------------------------------------------------------------------------
__device__ __forceinline__ unsigned int fkey(float f) {
    unsigned int u = __float_as_uint(f);
    return (u & 0x80000000u) ? ~u : (u | 0x80000000u);
}
__device__ __forceinline__ float keyToFloat(unsigned int u) {
    unsigned int b = (u & 0x80000000u) ? (u & 0x7FFFFFFFu) : ~u;
    return __uint_as_float(b);
}

__global__ __launch_bounds__(256) void topk_kernel(const float* __restrict__ gen,
                                                   const float* __restrict__ table,
                                                   float* __restrict__ out, int half_off) {
    const int b = blockIdx.x;
    const int tid = threadIdx.x;
    const unsigned short* __restrict__ rowh = d_scores_h + (size_t)b * VP_SZ;

    __shared__ int hist[NB_MAX];
    __shared__ int chunkSum[256];
    __shared__ unsigned int candKey[CAND_MAX];
    __shared__ int candIdx[CAND_MAX];
    __shared__ float gen_s[D_SZ];
    __shared__ unsigned int s_thresh;
    __shared__ int s_r, s_cand, s_count;

    // cache gen row
    if (tid < D_SZ / 4)
        *(float4*)&gen_s[tid * 4] = ((const float4*)(gen + (size_t)b * D_SZ))[tid];

    unsigned int mask = 0u, val = 0u;
    int r = R_SEL;
    const int shifts[3] = {20, 8, 0};
    const int bitsv[3] = {12, 12, 8};

    unsigned int thresh = 0u;
    for (int lvl = 0; lvl < 3; lvl++) {
        const int nb = 1 << bitsv[lvl];
        const int sh = shifts[lvl];

        for (int i = tid; i < nb; i += 256) hist[i] = 0;
        __syncthreads();

        for (int i = tid; i < V_SZ / 8; i += 256) {
            uint4 pk = ((const uint4*)rowh)[i];
            #pragma unroll
            for (int q = 0; q < 4; q++) {
                unsigned int w2 = (&pk.x)[q];
                float f0 = __half2float(__ushort_as_half((unsigned short)(w2 & 0xFFFF)));
                float f1 = __half2float(__ushort_as_half((unsigned short)(w2 >> 16)));
                unsigned int u;
                u = fkey(f0); if ((u & mask) == val) atomicAdd(&hist[(u >> sh) & (nb - 1)], 1);
                u = fkey(f1); if ((u & mask) == val) atomicAdd(&hist[(u >> sh) & (nb - 1)], 1);
            }
        }
        __syncthreads();

        const int cs = (nb + 255) / 256;
        {
            int lo = tid * cs;
            int hi = min(nb, lo + cs);
            int s = 0;
            for (int i = lo; i < hi; i++) s += hist[i];
            chunkSum[tid] = s;
        }
        __syncthreads();

        if (tid == 0) {
            int acc = 0, bsel = -1;
            for (int c = 255; c >= 0; c--) {
                int clo = c * cs;
                if (clo >= nb) continue;
                int chi = min(nb, clo + cs);
                if (acc + chunkSum[c] >= r) {
                    for (int bn = chi - 1; bn >= clo; bn--) {
                        if (acc + hist[bn] >= r) { bsel = bn; break; }
                        acc += hist[bn];
                    }
                    break;
                }
                acc += chunkSum[c];
            }
            int rn = r - acc;
            s_thresh = val | ((unsigned int)bsel << sh);
            s_r = rn;
            s_cand = (r - rn) + hist[bsel];
        }
        __syncthreads();
        thresh = s_thresh;
        int rn = s_r;
        int cand = s_cand;
        if (cand <= CAND_MAX || lvl == 2) break;
        mask |= (unsigned int)(nb - 1) << sh;
        val = thresh;
        r = rn;
    }

    // Collect candidate indices (approx key >= thresh)
    if (tid == 0) s_count = 0;
    __syncthreads();
    for (int i = tid; i < V_SZ / 8; i += 256) {
        uint4 pk = ((const uint4*)rowh)[i];
        #pragma unroll
        for (int q = 0; q < 4; q++) {
            unsigned int w2 = (&pk.x)[q];
            float f0 = __half2float(__ushort_as_half((unsigned short)(w2 & 0xFFFF)));
            float f1 = __half2float(__ushort_as_half((unsigned short)(w2 >> 16)));
            if (fkey(f0) >= thresh) { int p = atomicAdd(&s_count, 1); if (p < CAND_MAX) candIdx[p] = 8 * i + 2 * q; }
            if (fkey(f1) >= thresh) { int p = atomicAdd(&s_count, 1); if (p < CAND_MAX) candIdx[p] = 8 * i + 2 * q + 1; }
        }
    }
    __syncthreads();
    const int n = min(s_count, CAND_MAX);
    for (int i = n + tid; i < CAND_MAX; i += 256) {
        candKey[i] = 0u;
        candIdx[i] = 0x7FFFFFFF;
    }
    __syncthreads();

    // Exact fp32 rescore, sequential ascending-k fmaf (matches reference order)
    const float4* g4 = (const float4*)gen_s;
    for (int i = tid; i < n; i += 256) {
        const float4* t4 = (const float4*)(table + (size_t)candIdx[i] * D_SZ);
        float s = 0.0f;
        #pragma unroll
        for (int q = 0; q < D_SZ / 4; q++) {
            float4 a = g4[q];
            float4 t = __ldg(&t4[q]);
            s = fmaf(a.x, t.x, s);
            s = fmaf(a.y, t.y, s);
            s = fmaf(a.z, t.z, s);
            s = fmaf(a.w, t.w, s);
        }
        candKey[i] = fkey(s);
    }
    __syncthreads();

    // Bitonic sort: exact key desc, idx asc on ties
    for (int k = 2; k <= CAND_MAX; k <<= 1) {
        for (int j = k >> 1; j > 0; j >>= 1) {
            for (int i = tid; i < CAND_MAX; i += 256) {
                int ixj = i ^ j;
                if (ixj > i) {
                    unsigned int ki = candKey[i], kj = candKey[ixj];
                    int ii = candIdx[i], ij = candIdx[ixj];
                    bool before_ij = (ki > kj) || (ki == kj && ii < ij);
                    bool descRegion = ((i & k) == 0);
                    bool doswap = descRegion ? (!before_ij) : before_ij;
                    if (doswap) {
                        candKey[i] = kj; candKey[ixj] = ki;
                        candIdx[i] = ij; candIdx[ixj] = ii;
                    }
                }
            }
            __syncthreads();
        }
    }

    for (int i = tid; i < K_TOP; i += 256) {
        out[b * K_TOP + i] = keyToFloat(candKey[i]);
        out[half_off + b * K_TOP + i] = (float)candIdx[i];
    }
}

// ---------------------------------------------------------------------------
extern "C" void kernel_launch(void* const* d_in, const int* in_sizes, int n_in,
                              void* d_out, int out_size) {
    const float* gen   = (const float*)d_in[0];   // [1024,128] f32
    const void*  seeds = d_in[1];                 // [1024,100] int32 or int64
    const float* table = (const float*)d_in[2];   // [100000,128] f32
    float* out = (float*)d_out;

    detect_seed_kernel<<<1, 256>>>((const unsigned long long*)seeds);

    cudaFuncSetAttribute(gemm_tf32_kernel,
                         cudaFuncAttributeMaxDynamicSharedMemorySize, 32768);
    dim3 g(NT_TILES, B_SZ / 128);
    gemm_tf32_kernel<<<g, 256, 32768>>>(gen, table);

    pad_kernel<<<(B_SZ * (VP_SZ - V_SZ) + 255) / 256, 256>>>();
    mask_kernel<<<(B_SZ * S_SZ + 255) / 256, 256>>>(seeds);

    topk_kernel<<<B_SZ, 256>>>(gen, table, out, out_size / 2);
}

// round 5
// speedup vs baseline: 2.0558x; 1.6654x over previous
#include <cuda_runtime.h>
#include <cuda_fp16.h>
#include <stdint.h>

#define B_SZ 1024
#define D_SZ 128
#define V_SZ 100000
#define VP_SZ 100096           // padded to 782*128
#define S_SZ 100
#define K_TOP 500
#define R_SEL 640              // approx-rank cutoff
#define HALF_NEG_INF 0xFC00u

#define CAND_MAX 2048
#define NT_TILES 782

// ---------------------------------------------------------------------------
// Device globals
// ---------------------------------------------------------------------------
__device__ unsigned short d_scores_h[(size_t)B_SZ * VP_SZ];  // fp16 approx scores
__device__ __half d_g16[(size_t)B_SZ * D_SZ];
__device__ __half d_t16[(size_t)VP_SZ * D_SZ];               // zero-padded rows >= V
__device__ int d_seed_is32;

// ---------------------------------------------------------------------------
__device__ __forceinline__ void mma_f16(float* d, const unsigned* a, uint2 b) {
    asm volatile(
        "mma.sync.aligned.m16n8k16.row.col.f32.f16.f16.f32 "
        "{%0,%1,%2,%3}, {%4,%5,%6,%7}, {%8,%9}, {%0,%1,%2,%3};"
        : "+f"(d[0]), "+f"(d[1]), "+f"(d[2]), "+f"(d[3])
        : "r"(a[0]), "r"(a[1]), "r"(a[2]), "r"(a[3]), "r"(b.x), "r"(b.y));
}

__device__ __forceinline__ unsigned h2u(__half2 h) {
    return *reinterpret_cast<unsigned*>(&h);
}

// ---------------------------------------------------------------------------
// Seed-dtype detection (int64 vs silently-demoted int32): scan 1024 u64 words.
// int64 seeds < 100000 -> high words all zero; int32 data -> values in high
// words (1024 consecutive zero values impossible for random ints < 100000).
// ---------------------------------------------------------------------------
__global__ void detect_seed_kernel(const unsigned long long* __restrict__ seeds) {
    __shared__ unsigned int sflag;
    if (threadIdx.x == 0) sflag = 0u;
    __syncthreads();
    unsigned int loc = 0u;
    for (int i = threadIdx.x; i < 1024; i += blockDim.x)
        loc |= (unsigned int)(seeds[i] >> 32);
    if (loc) atomicOr(&sflag, 1u);
    __syncthreads();
    if (threadIdx.x == 0) d_seed_is32 = (sflag != 0u) ? 1 : 0;
}

// ---------------------------------------------------------------------------
// fp32 -> fp16 converters (8 halves per thread)
// ---------------------------------------------------------------------------
__global__ void convert_gen_kernel(const float* __restrict__ src) {
    int i = blockIdx.x * blockDim.x + threadIdx.x;
    if (i >= B_SZ * D_SZ / 8) return;
    float4 a = ((const float4*)src)[2 * i], b = ((const float4*)src)[2 * i + 1];
    uint4 o;
    o.x = h2u(__floats2half2_rn(a.x, a.y));
    o.y = h2u(__floats2half2_rn(a.z, a.w));
    o.z = h2u(__floats2half2_rn(b.x, b.y));
    o.w = h2u(__floats2half2_rn(b.z, b.w));
    ((uint4*)d_g16)[i] = o;
}

__global__ void convert_table_kernel(const float* __restrict__ src) {
    int i = blockIdx.x * blockDim.x + threadIdx.x;
    if (i >= VP_SZ * D_SZ / 8) return;
    int row = i >> 4;
    uint4 o = make_uint4(0u, 0u, 0u, 0u);
    if (row < V_SZ) {
        float4 a = ((const float4*)src)[2 * i], b = ((const float4*)src)[2 * i + 1];
        o.x = h2u(__floats2half2_rn(a.x, a.y));
        o.y = h2u(__floats2half2_rn(a.z, a.w));
        o.z = h2u(__floats2half2_rn(b.x, b.y));
        o.w = h2u(__floats2half2_rn(b.z, b.w));
    }
    ((uint4*)d_t16)[i] = o;
}

// ---------------------------------------------------------------------------
// fp16 HMMA GEMM: CTA 128x128, K=128 in one smem residency.
// 8 warps (4Mx2N), warp tile 32x64, mma.m16n8k16, 8 K-steps.
// Fragment-major XOR-swizzled smem: conflict-free lds.128 (A) / lds.64 (B).
//   A logical 16B-chunk: C = (ks*8 + mb)*32 + t          (2048 chunks, 32 KB)
//       phys: Cp = (C & ~7) | ((C ^ (C>>3) ^ (C>>8)) & 7)
//   B logical 8B-unit:   E = (ks*16 + nb)*32 + t          (4096 units, 32 KB)
//       phys: Ep = (E & ~15) | ((E ^ (E>>4) ^ (E>>9)) & 15)
// ---------------------------------------------------------------------------
__global__ __launch_bounds__(256) void gemm_f16_kernel() {
    extern __shared__ char smem[];
    unsigned* sA32 = (unsigned*)smem;            // 32 KB
    unsigned* sB32 = (unsigned*)(smem + 32768);  // 32 KB
    __half* sh = (__half*)smem;                  // epilogue stage (reuse)

    const int tid = threadIdx.x;
    const int lane = tid & 31;
    const int w = tid >> 5;
    const int warpM = w & 3;
    const int warpN = w >> 2;
    const int nt = blockIdx.x;
    const int by = blockIdx.y;

    const uint4* gA = (const uint4*)d_g16 + (size_t)(by * 128) * 16;
    const uint4* gB = (const uint4*)d_t16 + (size_t)(nt * 128) * 16;

    // ---- fill A ----
    #pragma unroll
    for (int it = 0; it < 8; it++) {
        const int u = tid + it * 256;
        const int r = u >> 4, q = u & 15;
        uint4 v = gA[r * 16 + q];
        const int ks = q >> 1;
        const int reg = ((r >> 3) & 1) + 2 * (q & 1);
        const int Cb = ks * 256 + ((r >> 4) & 7) * 32 + (r & 7) * 4;
        unsigned vv[4] = {v.x, v.y, v.z, v.w};
        #pragma unroll
        for (int i = 0; i < 4; i++) {
            const int C = Cb + i;
            const int Cp = (C & ~7) | ((C ^ (C >> 3) ^ (C >> 8)) & 7);
            sA32[Cp * 4 + reg] = vv[i];
        }
    }
    // ---- fill B ----
    #pragma unroll
    for (int it = 0; it < 8; it++) {
        const int u = tid + it * 256;
        const int c = u >> 4, q = u & 15;
        uint4 v = gB[c * 16 + q];
        const int ks = q >> 1;
        const int reg = q & 1;
        const int Eb = ks * 512 + (c >> 3) * 32 + (c & 7) * 4;
        unsigned vv[4] = {v.x, v.y, v.z, v.w};
        #pragma unroll
        for (int i = 0; i < 4; i++) {
            const int E = Eb + i;
            const int Ep = (E & ~15) | ((E ^ (E >> 4) ^ (E >> 9)) & 15);
            sB32[Ep * 2 + reg] = vv[i];
        }
    }
    __syncthreads();

    // ---- compute ----
    float acc[2][8][4];
    #pragma unroll
    for (int mf = 0; mf < 2; mf++)
        #pragma unroll
        for (int nf = 0; nf < 8; nf++)
            #pragma unroll
            for (int r = 0; r < 4; r++) acc[mf][nf][r] = 0.0f;

    #pragma unroll
    for (int ks = 0; ks < 8; ks++) {
        unsigned a[2][4];
        #pragma unroll
        for (int mf = 0; mf < 2; mf++) {
            const int C = ks * 256 + (warpM * 2 + mf) * 32 + lane;
            const int Cp = (C & ~7) | ((C ^ (C >> 3) ^ (C >> 8)) & 7);
            uint4 t4 = *(const uint4*)(&sA32[Cp * 4]);
            a[mf][0] = t4.x; a[mf][1] = t4.y; a[mf][2] = t4.z; a[mf][3] = t4.w;
        }
        #pragma unroll
        for (int nf = 0; nf < 8; nf++) {
            const int E = ks * 512 + (warpN * 8 + nf) * 32 + lane;
            const int Ep = (E & ~15) | ((E ^ (E >> 4) ^ (E >> 9)) & 15);
            const uint2 b2 = *(const uint2*)(&sB32[Ep * 2]);
            mma_f16(acc[0][nf], a[0], b2);
            mma_f16(acc[1][nf], a[1], b2);
        }
    }

    // ---- epilogue: regs -> smem fp16 -> coalesced gmem ----
    __syncthreads();
    #pragma unroll
    for (int mf = 0; mf < 2; mf++) {
        const int row = warpM * 32 + mf * 16 + (lane >> 2);
        #pragma unroll
        for (int nf = 0; nf < 8; nf++) {
            const int col = warpN * 64 + nf * 8 + (lane & 3) * 2;
            *(__half2*)(sh + row * 128 + col) =
                __floats2half2_rn(acc[mf][nf][0], acc[mf][nf][1]);
            *(__half2*)(sh + (row + 8) * 128 + col) =
                __floats2half2_rn(acc[mf][nf][2], acc[mf][nf][3]);
        }
    }
    __syncthreads();
    #pragma unroll
    for (int i = 0; i < 8; i++) {
        const int t = tid + i * 256;
        const int r = t >> 4;
        const int c16 = (t & 15) * 8;
        uint4 v = *(uint4*)(sh + r * 128 + c16);
        *(uint4*)&d_scores_h[(size_t)(by * 128 + r) * VP_SZ + nt * 128 + c16] = v;
    }
}

// ---------------------------------------------------------------------------
// Pad cols [V, VP) to -inf AND mask seed tracks, one kernel.
// ---------------------------------------------------------------------------
__global__ void maskpad_kernel(const void* __restrict__ seeds) {
    int i = blockIdx.x * blockDim.x + threadIdx.x;
    if (i < B_SZ * S_SZ) {
        long long idx;
        if (d_seed_is32) idx = (long long)((const int*)seeds)[i];
        else             idx = ((const long long*)seeds)[i];
        int b = i / S_SZ;
        d_scores_h[(size_t)b * VP_SZ + (size_t)idx] = (unsigned short)HALF_NEG_INF;
    }
    if (i < B_SZ * (VP_SZ - V_SZ)) {
        int b = i / (VP_SZ - V_SZ);
        int j = i % (VP_SZ - V_SZ);
        d_scores_h[(size_t)b * VP_SZ + V_SZ + j] = (unsigned short)HALF_NEG_INF;
    }
}

// ---------------------------------------------------------------------------
// Top-K: 16-bit-key radix select (single 4096-bin level — bins exhaust fp16
// space), collect candidate indices, exact fp32 sequential-k rescore
// (bit-matches reference), bitonic sort, emit top-500.
// ---------------------------------------------------------------------------
__device__ __forceinline__ unsigned key16(unsigned h) {   // h: 16-bit half bits
    return (h & 0x8000u) ? (h ^ 0xFFFFu) : (h | 0x8000u);
}
__device__ __forceinline__ unsigned int fkey(float f) {
    unsigned int u = __float_as_uint(f);
    return (u & 0x80000000u) ? ~u : (u | 0x80000000u);
}
__device__ __forceinline__ float keyToFloat(unsigned int u) {
    unsigned int b = (u & 0x80000000u) ? (u & 0x7FFFFFFFu) : ~u;
    return __uint_as_float(b);
}

__global__ __launch_bounds__(256) void topk_kernel(const float* __restrict__ gen,
                                                   const float* __restrict__ table,
                                                   float* __restrict__ out, int half_off) {
    const int b = blockIdx.x;
    const int tid = threadIdx.x;
    const unsigned short* __restrict__ rowh = d_scores_h + (size_t)b * VP_SZ;

    __shared__ int hist[4096];
    __shared__ int chunkSum[256];
    __shared__ unsigned int candKey[CAND_MAX];
    __shared__ int candIdx[CAND_MAX];
    __shared__ float gen_s[D_SZ];
    __shared__ unsigned s_thresh;
    __shared__ int s_count;

    if (tid < D_SZ / 4)
        *(float4*)&gen_s[tid * 4] = ((const float4*)(gen + (size_t)b * D_SZ))[tid];

    #pragma unroll
    for (int i = 0; i < 16; i++) hist[tid + i * 256] = 0;
    __syncthreads();

    // histogram on raw fp16 bits
    for (int i = tid; i < V_SZ / 8; i += 256) {
        uint4 pk = ((const uint4*)rowh)[i];
        #pragma unroll
        for (int q = 0; q < 4; q++) {
            unsigned w2 = (&pk.x)[q];
            atomicAdd(&hist[key16(w2 & 0xFFFFu) >> 4], 1);
            atomicAdd(&hist[key16(w2 >> 16) >> 4], 1);
        }
    }
    __syncthreads();

    {   // per-thread chunk sums (16 bins each)
        int s = 0;
        #pragma unroll
        for (int i = 0; i < 16; i++) s += hist[tid * 16 + i];
        chunkSum[tid] = s;
    }
    __syncthreads();

    if (tid == 0) {
        int acc = 0, bsel = 0;
        for (int c = 255; c >= 0; c--) {
            if (acc + chunkSum[c] >= R_SEL) {
                for (int bn = c * 16 + 15; bn >= c * 16; bn--) {
                    if (acc + hist[bn] >= R_SEL) { bsel = bn; break; }
                    acc += hist[bn];
                }
                break;
            }
            acc += chunkSum[c];
        }
        // acc = count strictly above boundary bin
        unsigned tk;
        if (acc + hist[bsel] <= CAND_MAX) tk = (unsigned)bsel << 4;
        else if (acc >= 520)              tk = (unsigned)(bsel + 1) << 4;
        else                              tk = (unsigned)bsel << 4;   // unreachable stats
        s_thresh = tk;
        s_count = 0;
    }
    __syncthreads();
    const unsigned thresh = s_thresh;

    // collect candidate indices
    for (int i = tid; i < V_SZ / 8; i += 256) {
        uint4 pk = ((const uint4*)rowh)[i];
        #pragma unroll
        for (int q = 0; q < 4; q++) {
            unsigned w2 = (&pk.x)[q];
            if (key16(w2 & 0xFFFFu) >= thresh) {
                int p = atomicAdd(&s_count, 1);
                if (p < CAND_MAX) candIdx[p] = 8 * i + 2 * q;
            }
            if (key16(w2 >> 16) >= thresh) {
                int p = atomicAdd(&s_count, 1);
                if (p < CAND_MAX) candIdx[p] = 8 * i + 2 * q + 1;
            }
        }
    }
    __syncthreads();
    const int n = min(s_count, CAND_MAX);
    for (int i = n + tid; i < CAND_MAX; i += 256) {
        candKey[i] = 0u;
        candIdx[i] = 0x7FFFFFFF;
    }
    __syncthreads();

    // exact fp32 rescore, sequential ascending-k fmaf (reference order)
    const float4* g4 = (const float4*)gen_s;
    for (int i = tid; i < n; i += 256) {
        const float4* t4 = (const float4*)(table + (size_t)candIdx[i] * D_SZ);
        float s = 0.0f;
        #pragma unroll
        for (int q = 0; q < D_SZ / 4; q++) {
            float4 a = g4[q];
            float4 t = __ldg(&t4[q]);
            s = fmaf(a.x, t.x, s);
            s = fmaf(a.y, t.y, s);
            s = fmaf(a.z, t.z, s);
            s = fmaf(a.w, t.w, s);
        }
        candKey[i] = fkey(s);
    }
    __syncthreads();

    // bitonic sort: exact key desc, idx asc on ties
    for (int k = 2; k <= CAND_MAX; k <<= 1) {
        for (int j = k >> 1; j > 0; j >>= 1) {
            for (int i = tid; i < CAND_MAX; i += 256) {
                int ixj = i ^ j;
                if (ixj > i) {
                    unsigned int ki = candKey[i], kj = candKey[ixj];
                    int ii = candIdx[i], ij = candIdx[ixj];
                    bool before_ij = (ki > kj) || (ki == kj && ii < ij);
                    bool descRegion = ((i & k) == 0);
                    bool doswap = descRegion ? (!before_ij) : before_ij;
                    if (doswap) {
                        candKey[i] = kj; candKey[ixj] = ki;
                        candIdx[i] = ij; candIdx[ixj] = ii;
                    }
                }
            }
            __syncthreads();
        }
    }

    for (int i = tid; i < K_TOP; i += 256) {
        out[b * K_TOP + i] = keyToFloat(candKey[i]);
        out[half_off + b * K_TOP + i] = (float)candIdx[i];
    }
}

// ---------------------------------------------------------------------------
extern "C" void kernel_launch(void* const* d_in, const int* in_sizes, int n_in,
                              void* d_out, int out_size) {
    const float* gen   = (const float*)d_in[0];   // [1024,128] f32
    const void*  seeds = d_in[1];                 // [1024,100] int32 or int64
    const float* table = (const float*)d_in[2];   // [100000,128] f32
    float* out = (float*)d_out;

    detect_seed_kernel<<<1, 256>>>((const unsigned long long*)seeds);

    convert_gen_kernel<<<(B_SZ * D_SZ / 8 + 255) / 256, 256>>>(gen);
    convert_table_kernel<<<(VP_SZ * D_SZ / 8 + 255) / 256, 256>>>(table);

    cudaFuncSetAttribute(gemm_f16_kernel,
                         cudaFuncAttributeMaxDynamicSharedMemorySize, 65536);
    dim3 g(NT_TILES, B_SZ / 128);
    gemm_f16_kernel<<<g, 256, 65536>>>();

    maskpad_kernel<<<(B_SZ * S_SZ + 255) / 256, 256>>>(seeds);

    topk_kernel<<<B_SZ, 256>>>(gen, table, out, out_size / 2);
}